// round 12
// baseline (speedup 1.0000x reference)
#include <cuda_runtime.h>
#include <cuda_bf16.h>
#include <cstdint>

#define N_NODES 50000
#define HID     256
#define NH      (N_NODES * HID)
#define MAX_E   2000000
#define NB_SCAN 49                      // ceil(50000/1024)
#define NBLK_M  391                     // ceil(50000/128)
#define CONV_BLKS 384                   // 3*32768/256

// ---------------- scratch (static device globals; no allocation) ------------
__device__ float g_buf1[NH];            // t = A@x, later p = A@h
__device__ float g_buf2[NH];            // h
__device__ float g_dinv[N_NODES];
__device__ int   g_deg[N_NODES];
__device__ int   g_rowptr[N_NODES + 1];
__device__ int   g_cur[N_NODES];
__device__ int   g_col[MAX_E];
__device__ int   g_bsum[NB_SCAN];
// weight images: per weight 128 kpairs x 256 cols, uint32 = 2 packed bf16 (k,k+1)
// column index pre-swizzled with n ^ ((kp&3)<<3)
__device__ uint32_t g_Bh[3 * 32768];
__device__ uint32_t g_Bl[3 * 32768];

// ---------------- bf16 pack helper -------------------------------------------
__device__ __forceinline__ uint32_t pack2bf16(float a, float b) {
    return (uint32_t)__bfloat16_as_ushort(__float2bfloat16(a))
         | ((uint32_t)__bfloat16_as_ushort(__float2bfloat16(b)) << 16);
}

// ---------------- merged: weight conversion + degree count -------------------
__global__ void k_count_conv(const int* __restrict__ ei, int E,
                             const float* __restrict__ W1,
                             const float* __restrict__ Wmu,
                             const float* __restrict__ Wls) {
    if (blockIdx.x < CONV_BLKS) {
        int idx = blockIdx.x * 256 + threadIdx.x;   // 3 * 32768 threads
        int w = idx >> 15;
        int e = idx & 32767;                        // kp*256 + n
        int kp = e >> 8, n = e & 255;
        const float* W = (w == 0) ? W1 : (w == 1) ? Wmu : Wls;
        float v0 = W[(2 * kp) * 256 + n];
        float v1 = W[(2 * kp + 1) * 256 + n];
        __nv_bfloat16 h0 = __float2bfloat16(v0);
        __nv_bfloat16 h1 = __float2bfloat16(v1);
        int ns = n ^ ((kp & 3) << 3);
        g_Bh[w * 32768 + kp * 256 + ns] =
            (uint32_t)__bfloat16_as_ushort(h0)
            | ((uint32_t)__bfloat16_as_ushort(h1) << 16);
        g_Bl[w * 32768 + kp * 256 + ns] =
            pack2bf16(v0 - __bfloat162float(h0), v1 - __bfloat162float(h1));
    } else {
        int i = (blockIdx.x - CONV_BLKS) * 256 + threadIdx.x;
        if (i < E) atomicAdd(&g_deg[ei[E + i]], 1);
    }
}

// ---------------- scan phase 1 ------------------------------------------------
__global__ void __launch_bounds__(1024) k_scan1() {
    __shared__ int sh[1024];
    int tid = threadIdx.x;
    int i = blockIdx.x * 1024 + tid;
    int v = (i < N_NODES) ? g_deg[i] : 0;
    if (i < N_NODES) g_dinv[i] = rsqrtf((float)(v + 1));   // +1 self loop
    sh[tid] = v;
    __syncthreads();
#pragma unroll
    for (int off = 1; off < 1024; off <<= 1) {
        int t = (tid >= off) ? sh[tid - off] : 0;
        __syncthreads();
        sh[tid] += t;
        __syncthreads();
    }
    if (i < N_NODES) g_rowptr[i] = sh[tid] - v;
    if (tid == 1023) g_bsum[blockIdx.x] = sh[1023];
}

// ---------------- scan phase 2 ------------------------------------------------
__global__ void __launch_bounds__(1024) k_scan2(int E) {
    __shared__ int pf[NB_SCAN];
    int tid = threadIdx.x;
    if (tid == 0) {
        int run = 0;
#pragma unroll
        for (int b = 0; b < NB_SCAN; b++) { pf[b] = run; run += g_bsum[b]; }
    }
    __syncthreads();
    int i = blockIdx.x * 1024 + tid;
    if (i < N_NODES) {
        int r = g_rowptr[i] + pf[blockIdx.x];
        g_rowptr[i] = r;
        g_cur[i] = r;
    }
    if (blockIdx.x == 0 && tid == 0) g_rowptr[N_NODES] = E;
}

__global__ void k_fill(const int* __restrict__ ei, int E) {
    int e = blockIdx.x * blockDim.x + threadIdx.x;
    if (e < E) {
        int d = ei[E + e];
        int pos = atomicAdd(&g_cur[d], 1);
        g_col[pos] = ei[e];
    }
}

// ---------------- CSR SpMM (proven 2-edge version) ----------------------------
__global__ void __launch_bounds__(256) k_spmm_csr(const float* __restrict__ X,
                                                  float* __restrict__ Y) {
    int node = blockIdx.x * 8 + (threadIdx.x >> 5);
    int lane = threadIdx.x & 31;
    if (node >= N_NODES) return;
    const float4* X4 = (const float4*)X;
    float4* Y4 = (float4*)Y;

    float4 s0 = make_float4(0.f, 0.f, 0.f, 0.f);
    float4 s1 = make_float4(0.f, 0.f, 0.f, 0.f);
    int beg = g_rowptr[node];
    int end = g_rowptr[node + 1];

    int e = beg;
    for (; e + 2 <= end; e += 2) {
        int sa = __ldg(&g_col[e]);
        int sb = __ldg(&g_col[e + 1]);
        float wa = g_dinv[sa];
        float wb = g_dinv[sb];
        const float4* pa = X4 + (size_t)sa * 64;
        const float4* pb = X4 + (size_t)sb * 64;
        float4 a0 = __ldg(pa + lane), a1 = __ldg(pa + lane + 32);
        float4 b0 = __ldg(pb + lane), b1 = __ldg(pb + lane + 32);
        s0.x += wa * a0.x + wb * b0.x; s0.y += wa * a0.y + wb * b0.y;
        s0.z += wa * a0.z + wb * b0.z; s0.w += wa * a0.w + wb * b0.w;
        s1.x += wa * a1.x + wb * b1.x; s1.y += wa * a1.y + wb * b1.y;
        s1.z += wa * a1.z + wb * b1.z; s1.w += wa * a1.w + wb * b1.w;
    }
    if (e < end) {
        int sa = __ldg(&g_col[e]);
        float wa = g_dinv[sa];
        const float4* pa = X4 + (size_t)sa * 64;
        float4 a0 = __ldg(pa + lane), a1 = __ldg(pa + lane + 32);
        s0.x += wa * a0.x; s0.y += wa * a0.y; s0.z += wa * a0.z; s0.w += wa * a0.w;
        s1.x += wa * a1.x; s1.y += wa * a1.y; s1.z += wa * a1.z; s1.w += wa * a1.w;
    }

    float dd = g_dinv[node];
    float dd2 = dd * dd;
    const float4* px = X4 + (size_t)node * 64;
    float4 x0 = __ldg(px + lane), x1 = __ldg(px + lane + 32);
    float4 o0, o1;
    o0.x = dd * s0.x + dd2 * x0.x; o0.y = dd * s0.y + dd2 * x0.y;
    o0.z = dd * s0.z + dd2 * x0.z; o0.w = dd * s0.w + dd2 * x0.w;
    o1.x = dd * s1.x + dd2 * x1.x; o1.y = dd * s1.y + dd2 * x1.y;
    o1.z = dd * s1.z + dd2 * x1.z; o1.w = dd * s1.w + dd2 * x1.w;
    Y4[(size_t)node * 64 + lane] = o0;
    Y4[(size_t)node * 64 + lane + 32] = o1;
}

// ---------------- threefry2x32 (JAX-exact) ----------------------------------
__device__ __forceinline__ uint32_t tf_rotl(uint32_t v, int s) {
    return (v << s) | (v >> (32 - s));
}

__device__ __forceinline__ uint2 threefry2x32(uint32_t k0, uint32_t k1,
                                              uint32_t x0, uint32_t x1) {
    uint32_t ks2 = k0 ^ k1 ^ 0x1BD11BDAu;
    x0 += k0; x1 += k1;
#define TF_R(r) { x0 += x1; x1 = tf_rotl(x1, r); x1 ^= x0; }
    TF_R(13) TF_R(15) TF_R(26) TF_R(6)   x0 += k1;  x1 += ks2 + 1u;
    TF_R(17) TF_R(29) TF_R(16) TF_R(24)  x0 += ks2; x1 += k0 + 2u;
    TF_R(13) TF_R(15) TF_R(26) TF_R(6)   x0 += k0;  x1 += k1 + 3u;
    TF_R(17) TF_R(29) TF_R(16) TF_R(24)  x0 += k1;  x1 += ks2 + 4u;
    TF_R(13) TF_R(15) TF_R(26) TF_R(6)   x0 += ks2; x1 += k0 + 5u;
#undef TF_R
    return make_uint2(x0, x1);
}

__device__ __forceinline__ float bits_to_eps(uint32_t bits) {
    float u01 = __uint_as_float((bits >> 9) | 0x3f800000u) - 1.0f;
    const float lo = __uint_as_float(0xBF7FFFFFu);
    const float span = 1.0f - lo;
    float v = __fadd_rn(__fmul_rn(u01, span), lo);
    v = fmaxf(lo, v);
    return 1.41421356f * erfinvf(v);
}

// ---------------- mma.sync m16n8k16 bf16 wrapper ------------------------------
__device__ __forceinline__ void mma16816(float* d, const uint32_t* a,
                                         uint32_t b0, uint32_t b1) {
    asm volatile(
        "mma.sync.aligned.m16n8k16.row.col.f32.bf16.bf16.f32 "
        "{%0,%1,%2,%3}, {%4,%5,%6,%7}, {%8,%9}, {%0,%1,%2,%3};"
        : "+f"(d[0]), "+f"(d[1]), "+f"(d[2]), "+f"(d[3])
        : "r"(a[0]), "r"(a[1]), "r"(a[2]), "r"(a[3]), "r"(b0), "r"(b1));
}

__device__ __forceinline__ uint32_t smem_u32(const void* p) {
    uint32_t a;
    asm("{ .reg .u64 t; cvta.to.shared.u64 t, %1; cvt.u32.u64 %0, t; }"
        : "=r"(a) : "l"(p));
    return a;
}

__device__ __forceinline__ void cp_async16(uint32_t dst, const void* src) {
    asm volatile("cp.async.cg.shared.global [%0], [%1], 16;"
                 :: "r"(dst), "l"(src) : "memory");
}

// ---------------- tensor-core GEMM via mma.sync -------------------------------
// C[M,256] = act(A[M,256] @ W + bias).  Split-bf16 3-term emulation.
// CTA: 128 rows x 256 cols, 512 threads (16 warps as 4m x 4n), warp tile 32x64.
// A prefetched into registers one chunk ahead; B double-buffered via cp.async.
// SMEM: bias @0, Ah @1024 (16KB), Al @17408 (16KB),
//       B buf0 hi @33792, lo @66560;  buf1 hi @99328, lo @132096 -> 164864 B
#define SMEM_MMA 164864

__global__ void __launch_bounds__(512, 1)
k_gemm_mma(const float* __restrict__ A, int M,
           const uint32_t* __restrict__ Bh, const uint32_t* __restrict__ Bl,
           const float* __restrict__ bias, float* __restrict__ C,
           int mode, const float* __restrict__ muIn, float* __restrict__ zOut) {
    extern __shared__ char smem[];
    float*    sBias = (float*)smem;
    uint32_t* sAh = (uint32_t*)(smem + 1024);
    uint32_t* sAl = (uint32_t*)(smem + 17408);
    uint32_t  bhAddr[2], blAddr[2];
    bhAddr[0] = smem_u32(smem + 33792);  blAddr[0] = smem_u32(smem + 66560);
    bhAddr[1] = smem_u32(smem + 99328);  blAddr[1] = smem_u32(smem + 132096);

    int tid = threadIdx.x;
    int l = tid & 31;
    int w = tid >> 5;           // 0..15
    int wm = w >> 2;            // 0..3  (rows wm*32)
    int wn = w & 3;             // 0..3  (cols wn*64)
    int rowBase = blockIdx.x * 128;

    if (tid < 256) sBias[tid] = bias[tid];

    float acc[2][8][4];
#pragma unroll
    for (int mt = 0; mt < 2; mt++)
#pragma unroll
        for (int nt = 0; nt < 8; nt++)
#pragma unroll
            for (int r = 0; r < 4; r++) acc[mt][nt][r] = 0.f;

    int arow = tid & 127;       // A conversion role: row
    int kseg = tid >> 7;        // 0..3 -> kpairs kseg*8..+7
    int grow = rowBase + arow;
    bool aok = grow < M;
    const float4* abase = (const float4*)(A + (size_t)grow * 256 + kseg * 16);

    // --- issue B chunk 0 copy (buf 0) + prefetch A chunk 0
    {
        const uint4* gh = (const uint4*)(Bh + 0 * 8192);
        const uint4* gl = (const uint4*)(Bl + 0 * 8192);
#pragma unroll
        for (int i = 0; i < 4; i++) {
            int j = tid + i * 512;
            cp_async16(bhAddr[0] + j * 16, gh + j);
            cp_async16(blAddr[0] + j * 16, gl + j);
        }
        asm volatile("cp.async.commit_group;" ::: "memory");
    }
    float4 f[4];
    if (aok) {
        f[0] = __ldg(abase + 0); f[1] = __ldg(abase + 1);
        f[2] = __ldg(abase + 2); f[3] = __ldg(abase + 3);
    } else {
        f[0] = f[1] = f[2] = f[3] = make_float4(0.f, 0.f, 0.f, 0.f);
    }

    for (int c = 0; c < 4; c++) {
        int buf = c & 1;
        __syncthreads();            // previous chunk's smem fully consumed
        // --- convert prefetched A registers -> split bf16 smem
        {
            const float* fv = (const float*)f;
#pragma unroll
            for (int i = 0; i < 8; i++) {
                int kp = kseg * 8 + i;
                float v0 = fv[2 * i], v1 = fv[2 * i + 1];
                __nv_bfloat16 h0 = __float2bfloat16(v0);
                __nv_bfloat16 h1 = __float2bfloat16(v1);
                uint32_t hp = (uint32_t)__bfloat16_as_ushort(h0)
                            | ((uint32_t)__bfloat16_as_ushort(h1) << 16);
                uint32_t lp = pack2bf16(v0 - __bfloat162float(h0),
                                        v1 - __bfloat162float(h1));
                int sr = arow ^ ((kp & 3) << 3);
                sAh[kp * 128 + sr] = hp;
                sAl[kp * 128 + sr] = lp;
            }
        }
        // --- issue next B chunk copy into alternate buffer; prefetch next A
        if (c < 3) {
            const uint4* gh = (const uint4*)(Bh + (c + 1) * 8192);
            const uint4* gl = (const uint4*)(Bl + (c + 1) * 8192);
            int nb = buf ^ 1;
#pragma unroll
            for (int i = 0; i < 4; i++) {
                int j = tid + i * 512;
                cp_async16(bhAddr[nb] + j * 16, gh + j);
                cp_async16(blAddr[nb] + j * 16, gl + j);
            }
            asm volatile("cp.async.commit_group;" ::: "memory");
            if (aok) {
                const float4* pn = abase + (c + 1) * 16;
                f[0] = __ldg(pn + 0); f[1] = __ldg(pn + 1);
                f[2] = __ldg(pn + 2); f[3] = __ldg(pn + 3);
            }
        }
        // --- wait for THIS chunk's B copy (allow next chunk's to stay pending)
        if (c < 3) {
            asm volatile("cp.async.wait_group 1;" ::: "memory");
        } else {
            asm volatile("cp.async.wait_group 0;" ::: "memory");
        }
        __syncthreads();

        const uint32_t* sBh = (const uint32_t*)(smem + (buf ? 99328 : 33792));
        const uint32_t* sBl = (const uint32_t*)(smem + (buf ? 132096 : 66560));

        // --- mma over 4 k-steps of 16
#pragma unroll
        for (int ks = 0; ks < 4; ks++) {
            int kp0 = ks * 8 + (l & 3);
            int sw = (l & 3) << 3;
            uint32_t ah[2][4], al2[2][4];
#pragma unroll
            for (int mt = 0; mt < 2; mt++) {
                int r0 = wm * 32 + mt * 16 + (l >> 2);
                int i00 = kp0 * 128 + (r0 ^ sw);
                int i01 = kp0 * 128 + ((r0 + 8) ^ sw);
                int i10 = (kp0 + 4) * 128 + (r0 ^ sw);
                int i11 = (kp0 + 4) * 128 + ((r0 + 8) ^ sw);
                ah[mt][0] = sAh[i00]; ah[mt][1] = sAh[i01];
                ah[mt][2] = sAh[i10]; ah[mt][3] = sAh[i11];
                al2[mt][0] = sAl[i00]; al2[mt][1] = sAl[i01];
                al2[mt][2] = sAl[i10]; al2[mt][3] = sAl[i11];
            }
#pragma unroll
            for (int nt = 0; nt < 8; nt++) {
                int nc = wn * 64 + nt * 8 + (l >> 2);
                int nsw = nc ^ sw;
                uint32_t bh0 = sBh[kp0 * 256 + nsw];
                uint32_t bh1 = sBh[(kp0 + 4) * 256 + nsw];
                uint32_t bl0 = sBl[kp0 * 256 + nsw];
                uint32_t bl1 = sBl[(kp0 + 4) * 256 + nsw];
#pragma unroll
                for (int mt = 0; mt < 2; mt++) {
                    mma16816(acc[mt][nt], ah[mt], bh0, bh1);
                    mma16816(acc[mt][nt], ah[mt], bl0, bl1);
                    mma16816(acc[mt][nt], al2[mt], bh0, bh1);
                }
            }
        }
    }

#pragma unroll
    for (int mt = 0; mt < 2; mt++) {
        int r = rowBase + wm * 32 + mt * 16 + (l >> 2);
#pragma unroll
        for (int nt = 0; nt < 8; nt++) {
            int colb = wn * 64 + nt * 8 + 2 * (l & 3);
            float b0v = sBias[colb], b1v = sBias[colb + 1];
#pragma unroll
            for (int half = 0; half < 2; half++) {
                int rr = r + half * 8;
                if (rr >= M) continue;
                float v0 = acc[mt][nt][half * 2 + 0] + b0v;
                float v1 = acc[mt][nt][half * 2 + 1] + b1v;
                if (mode == 1) { v0 = fmaxf(v0, 0.f); v1 = fmaxf(v1, 0.f); }
                size_t idx = (size_t)rr * 256 + colb;
                *(float2*)(C + idx) = make_float2(v0, v1);
                if (mode == 2) {
                    float2 m = *(const float2*)(muIn + idx);
                    uint2 r0 = threefry2x32(0u, 1u, 0u, (uint32_t)idx);
                    uint2 r1 = threefry2x32(0u, 1u, 0u, (uint32_t)idx + 1u);
                    float z0 = m.x + expf(v0) * bits_to_eps(r0.x ^ r0.y);
                    float z1 = m.y + expf(v1) * bits_to_eps(r1.x ^ r1.y);
                    *(float2*)(zOut + idx) = make_float2(z0, z1);
                }
            }
        }
    }
}

// ---------------- launch ------------------------------------------------------
extern "C" void kernel_launch(void* const* d_in, const int* in_sizes, int n_in,
                              void* d_out, int out_size) {
    const float* x   = (const float*)d_in[0];
    const int*   ei  = (const int*)d_in[1];
    const float* W1  = (const float*)d_in[2];
    const float* b1  = (const float*)d_in[3];
    const float* Wmu = (const float*)d_in[4];
    const float* bmu = (const float*)d_in[5];
    const float* Wls = (const float*)d_in[6];
    const float* bls = (const float*)d_in[7];
    int E = in_sizes[1] / 2;

    float* out = (float*)d_out;
    float* z   = out;
    float* mu  = out + (size_t)NH;
    float* ls  = out + 2 * (size_t)NH;

    float* buf1; float* buf2; int* degp; void* bhp; void* blp;
    cudaGetSymbolAddress((void**)&buf1, g_buf1);
    cudaGetSymbolAddress((void**)&buf2, g_buf2);
    cudaGetSymbolAddress((void**)&degp, g_deg);
    cudaGetSymbolAddress(&bhp, g_Bh);
    cudaGetSymbolAddress(&blp, g_Bl);
    const uint32_t* Bh = (const uint32_t*)bhp;
    const uint32_t* Bl = (const uint32_t*)blp;

    cudaFuncSetAttribute(k_gemm_mma,
                         cudaFuncAttributeMaxDynamicSharedMemorySize, SMEM_MMA);

    dim3 gspmm((N_NODES + 7) / 8);
    int cntBlks = CONV_BLKS + (E + 255) / 256;

    cudaMemsetAsync(degp, 0, N_NODES * sizeof(int));
    k_count_conv<<<cntBlks, 256>>>(ei, E, W1, Wmu, Wls);   // 1
    k_scan1<<<NB_SCAN, 1024>>>();                          // 2
    k_scan2<<<NB_SCAN, 1024>>>(E);                         // 3
    k_fill<<<(E + 255) / 256, 256>>>(ei, E);               // 4 <- profiled
    // t = A_norm @ x -> buf1
    k_spmm_csr<<<gspmm, 256>>>(x, buf1);
    // h = relu(t @ W1 + b1) -> buf2
    k_gemm_mma<<<NBLK_M, 512, SMEM_MMA>>>(buf1, N_NODES, Bh, Bl, b1,
                                          buf2, 1, nullptr, nullptr);
    // p = A_norm @ h -> buf1
    k_spmm_csr<<<gspmm, 256>>>(buf2, buf1);
    // mu
    k_gemm_mma<<<NBLK_M, 512, SMEM_MMA>>>(buf1, N_NODES, Bh + 32768, Bl + 32768,
                                          bmu, mu, 0, nullptr, nullptr);
    // ls + fused z
    k_gemm_mma<<<NBLK_M, 512, SMEM_MMA>>>(buf1, N_NODES, Bh + 65536, Bl + 65536,
                                          bls, ls, 2, mu, z);
}

// round 13
// speedup vs baseline: 1.0351x; 1.0351x over previous
#include <cuda_runtime.h>
#include <cuda_bf16.h>
#include <cstdint>

#define N_NODES 50000
#define HID     256
#define NH      (N_NODES * HID)
#define MAX_E   2000000
#define NB_SCAN 49                      // ceil(50000/1024)
#define NBLK_M  782                     // ceil(50000/64)
#define CONV_BLKS 384                   // 3*32768/256

// ---------------- scratch (static device globals; no allocation) ------------
__device__ float g_buf1[NH];            // t = A@x, later p = A@h
__device__ float g_buf2[NH];            // h
__device__ float g_dinv[N_NODES];
__device__ int   g_deg[N_NODES];
__device__ int   g_rowptr[N_NODES + 1];
__device__ int   g_cur[N_NODES];
__device__ int   g_col[MAX_E];
__device__ int   g_bsum[NB_SCAN];
// weight images: per weight 128 kpairs x 256 cols, uint32 = 2 packed bf16 (k,k+1)
// column index pre-swizzled with n ^ ((kp&3)<<3)
__device__ uint32_t g_Bh[3 * 32768];
__device__ uint32_t g_Bl[3 * 32768];

// ---------------- bf16 pack helper -------------------------------------------
__device__ __forceinline__ uint32_t pack2bf16(float a, float b) {
    return (uint32_t)__bfloat16_as_ushort(__float2bfloat16(a))
         | ((uint32_t)__bfloat16_as_ushort(__float2bfloat16(b)) << 16);
}

// ---------------- merged: weight conversion + degree count -------------------
__global__ void k_count_conv(const int* __restrict__ ei, int E,
                             const float* __restrict__ W1,
                             const float* __restrict__ Wmu,
                             const float* __restrict__ Wls) {
    if (blockIdx.x < CONV_BLKS) {
        int idx = blockIdx.x * 256 + threadIdx.x;   // 3 * 32768 threads
        int w = idx >> 15;
        int e = idx & 32767;                        // kp*256 + n
        int kp = e >> 8, n = e & 255;
        const float* W = (w == 0) ? W1 : (w == 1) ? Wmu : Wls;
        float v0 = W[(2 * kp) * 256 + n];
        float v1 = W[(2 * kp + 1) * 256 + n];
        __nv_bfloat16 h0 = __float2bfloat16(v0);
        __nv_bfloat16 h1 = __float2bfloat16(v1);
        int ns = n ^ ((kp & 3) << 3);
        g_Bh[w * 32768 + kp * 256 + ns] =
            (uint32_t)__bfloat16_as_ushort(h0)
            | ((uint32_t)__bfloat16_as_ushort(h1) << 16);
        g_Bl[w * 32768 + kp * 256 + ns] =
            pack2bf16(v0 - __bfloat162float(h0), v1 - __bfloat162float(h1));
    } else {
        int i = (blockIdx.x - CONV_BLKS) * 256 + threadIdx.x;
        if (i < E) atomicAdd(&g_deg[ei[E + i]], 1);
    }
}

// ---------------- scan phase 1 ------------------------------------------------
__global__ void __launch_bounds__(1024) k_scan1() {
    __shared__ int sh[1024];
    int tid = threadIdx.x;
    int i = blockIdx.x * 1024 + tid;
    int v = (i < N_NODES) ? g_deg[i] : 0;
    if (i < N_NODES) g_dinv[i] = rsqrtf((float)(v + 1));   // +1 self loop
    sh[tid] = v;
    __syncthreads();
#pragma unroll
    for (int off = 1; off < 1024; off <<= 1) {
        int t = (tid >= off) ? sh[tid - off] : 0;
        __syncthreads();
        sh[tid] += t;
        __syncthreads();
    }
    if (i < N_NODES) g_rowptr[i] = sh[tid] - v;
    if (tid == 1023) g_bsum[blockIdx.x] = sh[1023];
}

// ---------------- scan phase 2 ------------------------------------------------
__global__ void __launch_bounds__(1024) k_scan2(int E) {
    __shared__ int pf[NB_SCAN];
    int tid = threadIdx.x;
    if (tid == 0) {
        int run = 0;
#pragma unroll
        for (int b = 0; b < NB_SCAN; b++) { pf[b] = run; run += g_bsum[b]; }
    }
    __syncthreads();
    int i = blockIdx.x * 1024 + tid;
    if (i < N_NODES) {
        int r = g_rowptr[i] + pf[blockIdx.x];
        g_rowptr[i] = r;
        g_cur[i] = r;
    }
    if (blockIdx.x == 0 && tid == 0) g_rowptr[N_NODES] = E;
}

__global__ void k_fill(const int* __restrict__ ei, int E) {
    int e = blockIdx.x * blockDim.x + threadIdx.x;
    if (e < E) {
        int d = ei[E + e];
        int pos = atomicAdd(&g_cur[d], 1);
        g_col[pos] = ei[e];
    }
}

// ---------------- CSR SpMM: Y[d] = dd * sum_s dinv[s]*X[s] + dd^2 * X[d] ----
// one warp per node; index loads software-pipelined one iteration ahead so the
// row gathers issue immediately at iteration start (breaks idx->gather chain)
__global__ void __launch_bounds__(256) k_spmm_csr(const float* __restrict__ X,
                                                  float* __restrict__ Y) {
    int node = blockIdx.x * 8 + (threadIdx.x >> 5);
    int lane = threadIdx.x & 31;
    if (node >= N_NODES) return;
    const float4* X4 = (const float4*)X;
    float4* Y4 = (float4*)Y;

    float4 s0 = make_float4(0.f, 0.f, 0.f, 0.f);
    float4 s1 = make_float4(0.f, 0.f, 0.f, 0.f);
    int beg = g_rowptr[node];
    int end = g_rowptr[node + 1];

    int e = beg;
    int sa = 0, sb = 0;
    bool have = (e + 2 <= end);
    if (have) { sa = __ldg(&g_col[e]); sb = __ldg(&g_col[e + 1]); }
    while (have) {
        const float4* pa = X4 + (size_t)sa * 64;
        const float4* pb = X4 + (size_t)sb * 64;
        float4 a0 = __ldg(pa + lane), a1 = __ldg(pa + lane + 32);
        float4 b0 = __ldg(pb + lane), b1 = __ldg(pb + lane + 32);
        float wa = g_dinv[sa];
        float wb = g_dinv[sb];
        e += 2;
        have = (e + 2 <= end);
        if (have) { sa = __ldg(&g_col[e]); sb = __ldg(&g_col[e + 1]); }
        s0.x += wa * a0.x + wb * b0.x; s0.y += wa * a0.y + wb * b0.y;
        s0.z += wa * a0.z + wb * b0.z; s0.w += wa * a0.w + wb * b0.w;
        s1.x += wa * a1.x + wb * b1.x; s1.y += wa * a1.y + wb * b1.y;
        s1.z += wa * a1.z + wb * b1.z; s1.w += wa * a1.w + wb * b1.w;
    }
    for (; e < end; e++) {
        int sr = __ldg(&g_col[e]);
        float wr = g_dinv[sr];
        const float4* pr = X4 + (size_t)sr * 64;
        float4 a0 = __ldg(pr + lane), a1 = __ldg(pr + lane + 32);
        s0.x += wr * a0.x; s0.y += wr * a0.y; s0.z += wr * a0.z; s0.w += wr * a0.w;
        s1.x += wr * a1.x; s1.y += wr * a1.y; s1.z += wr * a1.z; s1.w += wr * a1.w;
    }

    float dd = g_dinv[node];
    float dd2 = dd * dd;
    const float4* px = X4 + (size_t)node * 64;
    float4 x0 = __ldg(px + lane), x1 = __ldg(px + lane + 32);
    float4 o0, o1;
    o0.x = dd * s0.x + dd2 * x0.x; o0.y = dd * s0.y + dd2 * x0.y;
    o0.z = dd * s0.z + dd2 * x0.z; o0.w = dd * s0.w + dd2 * x0.w;
    o1.x = dd * s1.x + dd2 * x1.x; o1.y = dd * s1.y + dd2 * x1.y;
    o1.z = dd * s1.z + dd2 * x1.z; o1.w = dd * s1.w + dd2 * x1.w;
    Y4[(size_t)node * 64 + lane] = o0;
    Y4[(size_t)node * 64 + lane + 32] = o1;
}

// ---------------- threefry2x32 (JAX-exact) ----------------------------------
__device__ __forceinline__ uint32_t tf_rotl(uint32_t v, int s) {
    return (v << s) | (v >> (32 - s));
}

__device__ __forceinline__ uint2 threefry2x32(uint32_t k0, uint32_t k1,
                                              uint32_t x0, uint32_t x1) {
    uint32_t ks2 = k0 ^ k1 ^ 0x1BD11BDAu;
    x0 += k0; x1 += k1;
#define TF_R(r) { x0 += x1; x1 = tf_rotl(x1, r); x1 ^= x0; }
    TF_R(13) TF_R(15) TF_R(26) TF_R(6)   x0 += k1;  x1 += ks2 + 1u;
    TF_R(17) TF_R(29) TF_R(16) TF_R(24)  x0 += ks2; x1 += k0 + 2u;
    TF_R(13) TF_R(15) TF_R(26) TF_R(6)   x0 += k0;  x1 += k1 + 3u;
    TF_R(17) TF_R(29) TF_R(16) TF_R(24)  x0 += k1;  x1 += ks2 + 4u;
    TF_R(13) TF_R(15) TF_R(26) TF_R(6)   x0 += ks2; x1 += k0 + 5u;
#undef TF_R
    return make_uint2(x0, x1);
}

__device__ __forceinline__ float bits_to_eps(uint32_t bits) {
    float u01 = __uint_as_float((bits >> 9) | 0x3f800000u) - 1.0f;
    const float lo = __uint_as_float(0xBF7FFFFFu);
    const float span = 1.0f - lo;
    float v = __fadd_rn(__fmul_rn(u01, span), lo);
    v = fmaxf(lo, v);
    return 1.41421356f * erfinvf(v);
}

// ---------------- mma.sync m16n8k16 bf16 wrapper ------------------------------
__device__ __forceinline__ void mma16816(float* d, const uint32_t* a,
                                         uint32_t b0, uint32_t b1) {
    asm volatile(
        "mma.sync.aligned.m16n8k16.row.col.f32.bf16.bf16.f32 "
        "{%0,%1,%2,%3}, {%4,%5,%6,%7}, {%8,%9}, {%0,%1,%2,%3};"
        : "+f"(d[0]), "+f"(d[1]), "+f"(d[2]), "+f"(d[3])
        : "r"(a[0]), "r"(a[1]), "r"(a[2]), "r"(a[3]), "r"(b0), "r"(b1));
}

// ---------------- tensor-core GEMM via mma.sync (R11 proven version) ----------
// C[M,256] = act(A[M,256] @ W + bias).  Split-bf16 3-term emulation.
// CTA: 64 rows x 256 cols, 256 threads (8 warps as 2m x 4n), warp tile 32x64.
// A-chunk prefetched into registers one chunk ahead; 2 CTAs/SM guaranteed.
// mode 0: plain (mu)   mode 1: relu (h)   mode 2: ls + fused z (reads muIn)
#define SMEM_MMA 82944

__global__ void __launch_bounds__(256, 2)
k_gemm_mma(const float* __restrict__ A, int M,
           const uint32_t* __restrict__ Bh, const uint32_t* __restrict__ Bl,
           const float* __restrict__ bias, float* __restrict__ C,
           int mode, const float* __restrict__ muIn, float* __restrict__ zOut) {
    extern __shared__ char smem[];
    float*    sBias = (float*)smem;
    uint32_t* sAh = (uint32_t*)(smem + 1024);
    uint32_t* sAl = (uint32_t*)(smem + 9216);
    uint32_t* sBh = (uint32_t*)(smem + 17408);
    uint32_t* sBl = (uint32_t*)(smem + 50176);

    int tid = threadIdx.x;
    int l = tid & 31;
    int w = tid >> 5;
    int wm = w >> 2;
    int wn = w & 3;
    int rowBase = blockIdx.x * 64;

    sBias[tid] = bias[tid];

    float acc[2][8][4];
#pragma unroll
    for (int mt = 0; mt < 2; mt++)
#pragma unroll
        for (int nt = 0; nt < 8; nt++)
#pragma unroll
            for (int r = 0; r < 4; r++) acc[mt][nt][r] = 0.f;

    int arow = tid & 63;
    int kseg = tid >> 6;
    int grow = rowBase + arow;
    bool aok = grow < M;
    const float4* abase = (const float4*)(A + (size_t)grow * 256 + kseg * 16);

    // prefetch chunk 0 A into registers
    float4 f[4];
    if (aok) {
        f[0] = __ldg(abase + 0); f[1] = __ldg(abase + 1);
        f[2] = __ldg(abase + 2); f[3] = __ldg(abase + 3);
    } else {
        f[0] = f[1] = f[2] = f[3] = make_float4(0.f, 0.f, 0.f, 0.f);
    }

    for (int c = 0; c < 4; c++) {
        __syncthreads();            // previous chunk's smem fully consumed
        // --- convert prefetched A registers -> split bf16 smem
        {
            const float* fv = (const float*)f;
#pragma unroll
            for (int i = 0; i < 8; i++) {
                int kp = kseg * 8 + i;
                float v0 = fv[2 * i], v1 = fv[2 * i + 1];
                __nv_bfloat16 h0 = __float2bfloat16(v0);
                __nv_bfloat16 h1 = __float2bfloat16(v1);
                uint32_t hp = (uint32_t)__bfloat16_as_ushort(h0)
                            | ((uint32_t)__bfloat16_as_ushort(h1) << 16);
                uint32_t lp = pack2bf16(v0 - __bfloat162float(h0),
                                        v1 - __bfloat162float(h1));
                int sr = arow ^ ((kp & 3) << 3);
                sAh[kp * 64 + sr] = hp;
                sAl[kp * 64 + sr] = lp;
            }
        }
        // --- B chunk: copy 32KB hi + 32KB lo (pre-swizzled images)
        {
            const uint4* gh = (const uint4*)(Bh + c * 8192);
            const uint4* gl = (const uint4*)(Bl + c * 8192);
            uint4* dh = (uint4*)sBh;
            uint4* dl = (uint4*)sBl;
#pragma unroll
            for (int i = 0; i < 8; i++) {
                dh[tid + i * 256] = __ldg(gh + tid + i * 256);
                dl[tid + i * 256] = __ldg(gl + tid + i * 256);
            }
        }
        __syncthreads();

        // --- prefetch next chunk's A while MMA runs
        if (c < 3 && aok) {
            const float4* pn = abase + (c + 1) * 16;
            f[0] = __ldg(pn + 0); f[1] = __ldg(pn + 1);
            f[2] = __ldg(pn + 2); f[3] = __ldg(pn + 3);
        }

        // --- mma over 4 k-steps of 16
#pragma unroll
        for (int ks = 0; ks < 4; ks++) {
            int kp0 = ks * 8 + (l & 3);
            int sw = (l & 3) << 3;
            uint32_t ah[2][4], al2[2][4];
#pragma unroll
            for (int mt = 0; mt < 2; mt++) {
                int r0 = wm * 32 + mt * 16 + (l >> 2);
                int i00 = kp0 * 64 + (r0 ^ sw);
                int i01 = kp0 * 64 + ((r0 + 8) ^ sw);
                int i10 = (kp0 + 4) * 64 + (r0 ^ sw);
                int i11 = (kp0 + 4) * 64 + ((r0 + 8) ^ sw);
                ah[mt][0] = sAh[i00]; ah[mt][1] = sAh[i01];
                ah[mt][2] = sAh[i10]; ah[mt][3] = sAh[i11];
                al2[mt][0] = sAl[i00]; al2[mt][1] = sAl[i01];
                al2[mt][2] = sAl[i10]; al2[mt][3] = sAl[i11];
            }
#pragma unroll
            for (int nt = 0; nt < 8; nt++) {
                int nc = wn * 64 + nt * 8 + (l >> 2);
                int nsw = nc ^ sw;
                uint32_t bh0 = sBh[kp0 * 256 + nsw];
                uint32_t bh1 = sBh[(kp0 + 4) * 256 + nsw];
                uint32_t bl0 = sBl[kp0 * 256 + nsw];
                uint32_t bl1 = sBl[(kp0 + 4) * 256 + nsw];
#pragma unroll
                for (int mt = 0; mt < 2; mt++) {
                    mma16816(acc[mt][nt], ah[mt], bh0, bh1);
                    mma16816(acc[mt][nt], ah[mt], bl0, bl1);
                    mma16816(acc[mt][nt], al2[mt], bh0, bh1);
                }
            }
        }
    }

#pragma unroll
    for (int mt = 0; mt < 2; mt++) {
        int r = rowBase + wm * 32 + mt * 16 + (l >> 2);
#pragma unroll
        for (int nt = 0; nt < 8; nt++) {
            int colb = wn * 64 + nt * 8 + 2 * (l & 3);
            float b0v = sBias[colb], b1v = sBias[colb + 1];
#pragma unroll
            for (int half = 0; half < 2; half++) {
                int rr = r + half * 8;
                if (rr >= M) continue;
                float v0 = acc[mt][nt][half * 2 + 0] + b0v;
                float v1 = acc[mt][nt][half * 2 + 1] + b1v;
                if (mode == 1) { v0 = fmaxf(v0, 0.f); v1 = fmaxf(v1, 0.f); }
                size_t idx = (size_t)rr * 256 + colb;
                *(float2*)(C + idx) = make_float2(v0, v1);
                if (mode == 2) {
                    float2 m = *(const float2*)(muIn + idx);
                    uint2 r0 = threefry2x32(0u, 1u, 0u, (uint32_t)idx);
                    uint2 r1 = threefry2x32(0u, 1u, 0u, (uint32_t)idx + 1u);
                    float z0 = m.x + expf(v0) * bits_to_eps(r0.x ^ r0.y);
                    float z1 = m.y + expf(v1) * bits_to_eps(r1.x ^ r1.y);
                    *(float2*)(zOut + idx) = make_float2(z0, z1);
                }
            }
        }
    }
}

// ---------------- launch ------------------------------------------------------
extern "C" void kernel_launch(void* const* d_in, const int* in_sizes, int n_in,
                              void* d_out, int out_size) {
    const float* x   = (const float*)d_in[0];
    const int*   ei  = (const int*)d_in[1];
    const float* W1  = (const float*)d_in[2];
    const float* b1  = (const float*)d_in[3];
    const float* Wmu = (const float*)d_in[4];
    const float* bmu = (const float*)d_in[5];
    const float* Wls = (const float*)d_in[6];
    const float* bls = (const float*)d_in[7];
    int E = in_sizes[1] / 2;

    float* out = (float*)d_out;
    float* z   = out;
    float* mu  = out + (size_t)NH;
    float* ls  = out + 2 * (size_t)NH;

    float* buf1; float* buf2; int* degp; void* bhp; void* blp;
    cudaGetSymbolAddress((void**)&buf1, g_buf1);
    cudaGetSymbolAddress((void**)&buf2, g_buf2);
    cudaGetSymbolAddress((void**)&degp, g_deg);
    cudaGetSymbolAddress(&bhp, g_Bh);
    cudaGetSymbolAddress(&blp, g_Bl);
    const uint32_t* Bh = (const uint32_t*)bhp;
    const uint32_t* Bl = (const uint32_t*)blp;

    cudaFuncSetAttribute(k_gemm_mma,
                         cudaFuncAttributeMaxDynamicSharedMemorySize, SMEM_MMA);

    dim3 gspmm((N_NODES + 7) / 8);
    int cntBlks = CONV_BLKS + (E + 255) / 256;

    cudaMemsetAsync(degp, 0, N_NODES * sizeof(int));
    k_count_conv<<<cntBlks, 256>>>(ei, E, W1, Wmu, Wls);   // 1
    k_scan1<<<NB_SCAN, 1024>>>();                          // 2
    k_scan2<<<NB_SCAN, 1024>>>(E);                         // 3
    k_fill<<<(E + 255) / 256, 256>>>(ei, E);               // 4 <- profiled
    // t = A_norm @ x -> buf1
    k_spmm_csr<<<gspmm, 256>>>(x, buf1);
    // h = relu(t @ W1 + b1) -> buf2
    k_gemm_mma<<<NBLK_M, 256, SMEM_MMA>>>(buf1, N_NODES, Bh, Bl, b1,
                                          buf2, 1, nullptr, nullptr);
    // p = A_norm @ h -> buf1
    k_spmm_csr<<<gspmm, 256>>>(buf2, buf1);
    // mu
    k_gemm_mma<<<NBLK_M, 256, SMEM_MMA>>>(buf1, N_NODES, Bh + 32768, Bl + 32768,
                                          bmu, mu, 0, nullptr, nullptr);
    // ls + fused z
    k_gemm_mma<<<NBLK_M, 256, SMEM_MMA>>>(buf1, N_NODES, Bh + 65536, Bl + 65536,
                                          bls, ls, 2, mu, z);
}

// round 14
// speedup vs baseline: 1.2464x; 1.2041x over previous
#include <cuda_runtime.h>
#include <cuda_bf16.h>
#include <cstdint>

#define N_NODES 50000
#define HID     256
#define NH      (N_NODES * HID)
#define MAX_E   2000000
#define NB_SCAN 49                      // ceil(50000/1024)
#define NBLK_M  782                     // ceil(50000/64)
#define CONV_BLKS 384                   // 3*32768/256

// ---------------- scratch (static device globals; no allocation) ------------
__device__ float g_buf1[NH];            // t = A@x, later p = A@h
__device__ float g_buf2[NH];            // h
__device__ float g_dinv[N_NODES];
__device__ int   g_deg[N_NODES];
__device__ int   g_rowptr[N_NODES + 1];
__device__ int   g_cur[N_NODES];
__device__ int   g_col[MAX_E];
__device__ int   g_bsum[NB_SCAN];
// weight images: per weight 128 kpairs x 256 cols, uint32 = 2 packed bf16 (k,k+1)
// column index pre-swizzled with n ^ ((kp&3)<<3)
__device__ uint32_t g_Bh[3 * 32768];
__device__ uint32_t g_Bl[3 * 32768];

// ---------------- bf16 pack helper -------------------------------------------
__device__ __forceinline__ uint32_t pack2bf16(float a, float b) {
    return (uint32_t)__bfloat16_as_ushort(__float2bfloat16(a))
         | ((uint32_t)__bfloat16_as_ushort(__float2bfloat16(b)) << 16);
}

// ---------------- merged: weight conversion + degree count -------------------
__global__ void k_count_conv(const int* __restrict__ ei, int E,
                             const float* __restrict__ W1,
                             const float* __restrict__ Wmu,
                             const float* __restrict__ Wls) {
    if (blockIdx.x < CONV_BLKS) {
        int idx = blockIdx.x * 256 + threadIdx.x;   // 3 * 32768 threads
        int w = idx >> 15;
        int e = idx & 32767;                        // kp*256 + n
        int kp = e >> 8, n = e & 255;
        const float* W = (w == 0) ? W1 : (w == 1) ? Wmu : Wls;
        float v0 = W[(2 * kp) * 256 + n];
        float v1 = W[(2 * kp + 1) * 256 + n];
        __nv_bfloat16 h0 = __float2bfloat16(v0);
        __nv_bfloat16 h1 = __float2bfloat16(v1);
        int ns = n ^ ((kp & 3) << 3);
        g_Bh[w * 32768 + kp * 256 + ns] =
            (uint32_t)__bfloat16_as_ushort(h0)
            | ((uint32_t)__bfloat16_as_ushort(h1) << 16);
        g_Bl[w * 32768 + kp * 256 + ns] =
            pack2bf16(v0 - __bfloat162float(h0), v1 - __bfloat162float(h1));
    } else {
        int i = (blockIdx.x - CONV_BLKS) * 256 + threadIdx.x;
        if (i < E) atomicAdd(&g_deg[ei[E + i]], 1);
    }
}

// ---------------- scan phase 1 ------------------------------------------------
__global__ void __launch_bounds__(1024) k_scan1() {
    __shared__ int sh[1024];
    int tid = threadIdx.x;
    int i = blockIdx.x * 1024 + tid;
    int v = (i < N_NODES) ? g_deg[i] : 0;
    if (i < N_NODES) g_dinv[i] = rsqrtf((float)(v + 1));   // +1 self loop
    sh[tid] = v;
    __syncthreads();
#pragma unroll
    for (int off = 1; off < 1024; off <<= 1) {
        int t = (tid >= off) ? sh[tid - off] : 0;
        __syncthreads();
        sh[tid] += t;
        __syncthreads();
    }
    if (i < N_NODES) g_rowptr[i] = sh[tid] - v;
    if (tid == 1023) g_bsum[blockIdx.x] = sh[1023];
}

// ---------------- scan phase 2 ------------------------------------------------
__global__ void __launch_bounds__(1024) k_scan2(int E) {
    __shared__ int pf[NB_SCAN];
    int tid = threadIdx.x;
    if (tid == 0) {
        int run = 0;
#pragma unroll
        for (int b = 0; b < NB_SCAN; b++) { pf[b] = run; run += g_bsum[b]; }
    }
    __syncthreads();
    int i = blockIdx.x * 1024 + tid;
    if (i < N_NODES) {
        int r = g_rowptr[i] + pf[blockIdx.x];
        g_rowptr[i] = r;
        g_cur[i] = r;
    }
    if (blockIdx.x == 0 && tid == 0) g_rowptr[N_NODES] = E;
}

__global__ void k_fill(const int* __restrict__ ei, int E) {
    int e = blockIdx.x * blockDim.x + threadIdx.x;
    if (e < E) {
        int d = ei[E + e];
        int pos = atomicAdd(&g_cur[d], 1);
        g_col[pos] = ei[e];
    }
}

// ---------------- CSR SpMM (R11 proven 2-edge version) ------------------------
__global__ void __launch_bounds__(256) k_spmm_csr(const float* __restrict__ X,
                                                  float* __restrict__ Y) {
    int node = blockIdx.x * 8 + (threadIdx.x >> 5);
    int lane = threadIdx.x & 31;
    if (node >= N_NODES) return;
    const float4* X4 = (const float4*)X;
    float4* Y4 = (float4*)Y;

    float4 s0 = make_float4(0.f, 0.f, 0.f, 0.f);
    float4 s1 = make_float4(0.f, 0.f, 0.f, 0.f);
    int beg = g_rowptr[node];
    int end = g_rowptr[node + 1];

    int e = beg;
    for (; e + 2 <= end; e += 2) {
        int sa = __ldg(&g_col[e]);
        int sb = __ldg(&g_col[e + 1]);
        float wa = g_dinv[sa];
        float wb = g_dinv[sb];
        const float4* pa = X4 + (size_t)sa * 64;
        const float4* pb = X4 + (size_t)sb * 64;
        float4 a0 = __ldg(pa + lane), a1 = __ldg(pa + lane + 32);
        float4 b0 = __ldg(pb + lane), b1 = __ldg(pb + lane + 32);
        s0.x += wa * a0.x + wb * b0.x; s0.y += wa * a0.y + wb * b0.y;
        s0.z += wa * a0.z + wb * b0.z; s0.w += wa * a0.w + wb * b0.w;
        s1.x += wa * a1.x + wb * b1.x; s1.y += wa * a1.y + wb * b1.y;
        s1.z += wa * a1.z + wb * b1.z; s1.w += wa * a1.w + wb * b1.w;
    }
    if (e < end) {
        int sa = __ldg(&g_col[e]);
        float wa = g_dinv[sa];
        const float4* pa = X4 + (size_t)sa * 64;
        float4 a0 = __ldg(pa + lane), a1 = __ldg(pa + lane + 32);
        s0.x += wa * a0.x; s0.y += wa * a0.y; s0.z += wa * a0.z; s0.w += wa * a0.w;
        s1.x += wa * a1.x; s1.y += wa * a1.y; s1.z += wa * a1.z; s1.w += wa * a1.w;
    }

    float dd = g_dinv[node];
    float dd2 = dd * dd;
    const float4* px = X4 + (size_t)node * 64;
    float4 x0 = __ldg(px + lane), x1 = __ldg(px + lane + 32);
    float4 o0, o1;
    o0.x = dd * s0.x + dd2 * x0.x; o0.y = dd * s0.y + dd2 * x0.y;
    o0.z = dd * s0.z + dd2 * x0.z; o0.w = dd * s0.w + dd2 * x0.w;
    o1.x = dd * s1.x + dd2 * x1.x; o1.y = dd * s1.y + dd2 * x1.y;
    o1.z = dd * s1.z + dd2 * x1.z; o1.w = dd * s1.w + dd2 * x1.w;
    Y4[(size_t)node * 64 + lane] = o0;
    Y4[(size_t)node * 64 + lane + 32] = o1;
}

// ---------------- threefry2x32 (JAX-exact) ----------------------------------
__device__ __forceinline__ uint32_t tf_rotl(uint32_t v, int s) {
    return (v << s) | (v >> (32 - s));
}

__device__ __forceinline__ uint2 threefry2x32(uint32_t k0, uint32_t k1,
                                              uint32_t x0, uint32_t x1) {
    uint32_t ks2 = k0 ^ k1 ^ 0x1BD11BDAu;
    x0 += k0; x1 += k1;
#define TF_R(r) { x0 += x1; x1 = tf_rotl(x1, r); x1 ^= x0; }
    TF_R(13) TF_R(15) TF_R(26) TF_R(6)   x0 += k1;  x1 += ks2 + 1u;
    TF_R(17) TF_R(29) TF_R(16) TF_R(24)  x0 += ks2; x1 += k0 + 2u;
    TF_R(13) TF_R(15) TF_R(26) TF_R(6)   x0 += k0;  x1 += k1 + 3u;
    TF_R(17) TF_R(29) TF_R(16) TF_R(24)  x0 += k1;  x1 += ks2 + 4u;
    TF_R(13) TF_R(15) TF_R(26) TF_R(6)   x0 += ks2; x1 += k0 + 5u;
#undef TF_R
    return make_uint2(x0, x1);
}

__device__ __forceinline__ float bits_to_eps(uint32_t bits) {
    float u01 = __uint_as_float((bits >> 9) | 0x3f800000u) - 1.0f;
    const float lo = __uint_as_float(0xBF7FFFFFu);
    const float span = 1.0f - lo;
    float v = __fadd_rn(__fmul_rn(u01, span), lo);
    v = fmaxf(lo, v);
    return 1.41421356f * erfinvf(v);
}

// ---------------- mma.sync m16n8k16 bf16 wrapper ------------------------------
__device__ __forceinline__ void mma16816(float* d, const uint32_t* a,
                                         uint32_t b0, uint32_t b1) {
    asm volatile(
        "mma.sync.aligned.m16n8k16.row.col.f32.bf16.bf16.f32 "
        "{%0,%1,%2,%3}, {%4,%5,%6,%7}, {%8,%9}, {%0,%1,%2,%3};"
        : "+f"(d[0]), "+f"(d[1]), "+f"(d[2]), "+f"(d[3])
        : "r"(a[0]), "r"(a[1]), "r"(a[2]), "r"(a[3]), "r"(b0), "r"(b1));
}

#define SMEM_MMA 82944

// ---------------- tensor-core GEMM (single weight, relu) — R11 proven ---------
__global__ void __launch_bounds__(256, 2)
k_gemm_mma(const float* __restrict__ A, int M,
           const uint32_t* __restrict__ Bh, const uint32_t* __restrict__ Bl,
           const float* __restrict__ bias, float* __restrict__ C) {
    extern __shared__ char smem[];
    float*    sBias = (float*)smem;
    uint32_t* sAh = (uint32_t*)(smem + 1024);
    uint32_t* sAl = (uint32_t*)(smem + 9216);
    uint32_t* sBh = (uint32_t*)(smem + 17408);
    uint32_t* sBl = (uint32_t*)(smem + 50176);

    int tid = threadIdx.x;
    int l = tid & 31;
    int w = tid >> 5;
    int wm = w >> 2;
    int wn = w & 3;
    int rowBase = blockIdx.x * 64;

    sBias[tid] = bias[tid];

    float acc[2][8][4];
#pragma unroll
    for (int mt = 0; mt < 2; mt++)
#pragma unroll
        for (int nt = 0; nt < 8; nt++)
#pragma unroll
            for (int r = 0; r < 4; r++) acc[mt][nt][r] = 0.f;

    int arow = tid & 63;
    int kseg = tid >> 6;
    int grow = rowBase + arow;
    bool aok = grow < M;
    const float4* abase = (const float4*)(A + (size_t)grow * 256 + kseg * 16);

    float4 f[4];
    if (aok) {
        f[0] = __ldg(abase + 0); f[1] = __ldg(abase + 1);
        f[2] = __ldg(abase + 2); f[3] = __ldg(abase + 3);
    } else {
        f[0] = f[1] = f[2] = f[3] = make_float4(0.f, 0.f, 0.f, 0.f);
    }

    for (int c = 0; c < 4; c++) {
        __syncthreads();
        {
            const float* fv = (const float*)f;
#pragma unroll
            for (int i = 0; i < 8; i++) {
                int kp = kseg * 8 + i;
                float v0 = fv[2 * i], v1 = fv[2 * i + 1];
                __nv_bfloat16 h0 = __float2bfloat16(v0);
                __nv_bfloat16 h1 = __float2bfloat16(v1);
                uint32_t hp = (uint32_t)__bfloat16_as_ushort(h0)
                            | ((uint32_t)__bfloat16_as_ushort(h1) << 16);
                uint32_t lp = pack2bf16(v0 - __bfloat162float(h0),
                                        v1 - __bfloat162float(h1));
                int sr = arow ^ ((kp & 3) << 3);
                sAh[kp * 64 + sr] = hp;
                sAl[kp * 64 + sr] = lp;
            }
        }
        {
            const uint4* gh = (const uint4*)(Bh + c * 8192);
            const uint4* gl = (const uint4*)(Bl + c * 8192);
            uint4* dh = (uint4*)sBh;
            uint4* dl = (uint4*)sBl;
#pragma unroll
            for (int i = 0; i < 8; i++) {
                dh[tid + i * 256] = __ldg(gh + tid + i * 256);
                dl[tid + i * 256] = __ldg(gl + tid + i * 256);
            }
        }
        __syncthreads();

        if (c < 3 && aok) {
            const float4* pn = abase + (c + 1) * 16;
            f[0] = __ldg(pn + 0); f[1] = __ldg(pn + 1);
            f[2] = __ldg(pn + 2); f[3] = __ldg(pn + 3);
        }

#pragma unroll
        for (int ks = 0; ks < 4; ks++) {
            int kp0 = ks * 8 + (l & 3);
            int sw = (l & 3) << 3;
            uint32_t ah[2][4], al2[2][4];
#pragma unroll
            for (int mt = 0; mt < 2; mt++) {
                int r0 = wm * 32 + mt * 16 + (l >> 2);
                int i00 = kp0 * 64 + (r0 ^ sw);
                int i01 = kp0 * 64 + ((r0 + 8) ^ sw);
                int i10 = (kp0 + 4) * 64 + (r0 ^ sw);
                int i11 = (kp0 + 4) * 64 + ((r0 + 8) ^ sw);
                ah[mt][0] = sAh[i00]; ah[mt][1] = sAh[i01];
                ah[mt][2] = sAh[i10]; ah[mt][3] = sAh[i11];
                al2[mt][0] = sAl[i00]; al2[mt][1] = sAl[i01];
                al2[mt][2] = sAl[i10]; al2[mt][3] = sAl[i11];
            }
#pragma unroll
            for (int nt = 0; nt < 8; nt++) {
                int nc = wn * 64 + nt * 8 + (l >> 2);
                int nsw = nc ^ sw;
                uint32_t bh0 = sBh[kp0 * 256 + nsw];
                uint32_t bh1 = sBh[(kp0 + 4) * 256 + nsw];
                uint32_t bl0 = sBl[kp0 * 256 + nsw];
                uint32_t bl1 = sBl[(kp0 + 4) * 256 + nsw];
#pragma unroll
                for (int mt = 0; mt < 2; mt++) {
                    mma16816(acc[mt][nt], ah[mt], bh0, bh1);
                    mma16816(acc[mt][nt], ah[mt], bl0, bl1);
                    mma16816(acc[mt][nt], al2[mt], bh0, bh1);
                }
            }
        }
    }

#pragma unroll
    for (int mt = 0; mt < 2; mt++) {
        int r = rowBase + wm * 32 + mt * 16 + (l >> 2);
#pragma unroll
        for (int nt = 0; nt < 8; nt++) {
            int colb = wn * 64 + nt * 8 + 2 * (l & 3);
            float b0v = sBias[colb], b1v = sBias[colb + 1];
#pragma unroll
            for (int half = 0; half < 2; half++) {
                int rr = r + half * 8;
                if (rr >= M) continue;
                float v0 = fmaxf(acc[mt][nt][half * 2 + 0] + b0v, 0.f);
                float v1 = fmaxf(acc[mt][nt][half * 2 + 1] + b1v, 0.f);
                *(float2*)(C + (size_t)rr * 256 + colb) = make_float2(v0, v1);
            }
        }
    }
}

// ---------------- dual column-split GEMM: mu & ls & z -------------------------
// Each CTA: 64 rows x 128 cols of BOTH mu and ls (+ fused z).
// grid = 2*NBLK_M; blockIdx: nb = bx>>1 (row block), hf = bx&1 (column half).
// Same acc registers (64) and same smem budget (82944) as single GEMM.
// SMEM: bias0 @0 (512B), bias1 @512, Ah @1024 (8KB), Al @9216 (8KB),
//       Bh0 @17408 (16KB), Bl0 @33792, Bh1 @50176, Bl1 @66560 -> 82944
__global__ void __launch_bounds__(256, 2)
k_gemm_dual2(const float* __restrict__ A, int M,
             const uint32_t* __restrict__ Bh0, const uint32_t* __restrict__ Bl0,
             const float* __restrict__ bias0,
             const uint32_t* __restrict__ Bh1, const uint32_t* __restrict__ Bl1,
             const float* __restrict__ bias1,
             float* __restrict__ Cmu, float* __restrict__ Cls,
             float* __restrict__ zOut) {
    extern __shared__ char smem[];
    float*    sB0 = (float*)smem;
    float*    sB1 = (float*)(smem + 512);
    uint32_t* sAh = (uint32_t*)(smem + 1024);
    uint32_t* sAl = (uint32_t*)(smem + 9216);
    uint32_t* sBh0 = (uint32_t*)(smem + 17408);
    uint32_t* sBl0 = (uint32_t*)(smem + 33792);
    uint32_t* sBh1 = (uint32_t*)(smem + 50176);
    uint32_t* sBl1 = (uint32_t*)(smem + 66560);

    int tid = threadIdx.x;
    int l = tid & 31;
    int w = tid >> 5;
    int wm = w >> 2;            // 0..1 (rows wm*32)
    int wn = w & 3;             // 0..3 (cols wn*32 within 128)
    int nb = blockIdx.x >> 1;
    int hf = blockIdx.x & 1;
    int rowBase = nb * 64;
    int colOff = hf * 128;

    if (tid < 128) {
        sB0[tid] = bias0[colOff + tid];
        sB1[tid] = bias1[colOff + tid];
    }

    float acc0[2][4][4], acc1[2][4][4];
#pragma unroll
    for (int mt = 0; mt < 2; mt++)
#pragma unroll
        for (int nt = 0; nt < 4; nt++)
#pragma unroll
            for (int r = 0; r < 4; r++) { acc0[mt][nt][r] = 0.f; acc1[mt][nt][r] = 0.f; }

    int arow = tid & 63;
    int kseg = tid >> 6;
    int grow = rowBase + arow;
    bool aok = grow < M;
    const float4* abase = (const float4*)(A + (size_t)grow * 256 + kseg * 16);

    float4 f[4];
    if (aok) {
        f[0] = __ldg(abase + 0); f[1] = __ldg(abase + 1);
        f[2] = __ldg(abase + 2); f[3] = __ldg(abase + 3);
    } else {
        f[0] = f[1] = f[2] = f[3] = make_float4(0.f, 0.f, 0.f, 0.f);
    }

    for (int c = 0; c < 4; c++) {
        __syncthreads();
        // --- A convert (same as single GEMM)
        {
            const float* fv = (const float*)f;
#pragma unroll
            for (int i = 0; i < 8; i++) {
                int kp = kseg * 8 + i;
                float v0 = fv[2 * i], v1 = fv[2 * i + 1];
                __nv_bfloat16 h0 = __float2bfloat16(v0);
                __nv_bfloat16 h1 = __float2bfloat16(v1);
                uint32_t hp = (uint32_t)__bfloat16_as_ushort(h0)
                            | ((uint32_t)__bfloat16_as_ushort(h1) << 16);
                uint32_t lp = pack2bf16(v0 - __bfloat162float(h0),
                                        v1 - __bfloat162float(h1));
                int sr = arow ^ ((kp & 3) << 3);
                sAh[kp * 64 + sr] = hp;
                sAl[kp * 64 + sr] = lp;
            }
        }
        // --- B half-column copy for both weights (4 x 16KB)
        // image row = 64 uint4 (256 uint32); half offset = hf*32 uint4
        {
            int row = tid >> 5;          // j>>5 for j = tid..; do 4 per thread
#pragma unroll
            for (int i = 0; i < 4; i++) {
                int j = tid + i * 256;          // 0..1023
                int r2 = j >> 5;                 // row within chunk, 0..31
                int cj = j & 31;                 // uint4 within half-row
                size_t src = (size_t)(c * 32 + r2) * 64 + hf * 32 + cj;
                ((uint4*)sBh0)[j] = __ldg((const uint4*)Bh0 + src);
                ((uint4*)sBl0)[j] = __ldg((const uint4*)Bl0 + src);
                ((uint4*)sBh1)[j] = __ldg((const uint4*)Bh1 + src);
                ((uint4*)sBl1)[j] = __ldg((const uint4*)Bl1 + src);
            }
            (void)row;
        }
        __syncthreads();

        if (c < 3 && aok) {
            const float4* pn = abase + (c + 1) * 16;
            f[0] = __ldg(pn + 0); f[1] = __ldg(pn + 1);
            f[2] = __ldg(pn + 2); f[3] = __ldg(pn + 3);
        }

#pragma unroll
        for (int ks = 0; ks < 4; ks++) {
            int kp0 = ks * 8 + (l & 3);
            int sw = (l & 3) << 3;
            uint32_t ah[2][4], al2[2][4];
#pragma unroll
            for (int mt = 0; mt < 2; mt++) {
                int r0 = wm * 32 + mt * 16 + (l >> 2);
                int i00 = kp0 * 64 + (r0 ^ sw);
                int i01 = kp0 * 64 + ((r0 + 8) ^ sw);
                int i10 = (kp0 + 4) * 64 + (r0 ^ sw);
                int i11 = (kp0 + 4) * 64 + ((r0 + 8) ^ sw);
                ah[mt][0] = sAh[i00]; ah[mt][1] = sAh[i01];
                ah[mt][2] = sAh[i10]; ah[mt][3] = sAh[i11];
                al2[mt][0] = sAl[i00]; al2[mt][1] = sAl[i01];
                al2[mt][2] = sAl[i10]; al2[mt][3] = sAl[i11];
            }
#pragma unroll
            for (int nt = 0; nt < 4; nt++) {
                int nc = wn * 32 + nt * 8 + (l >> 2);      // 0..127
                int nsw = nc ^ sw;
                int ix0 = kp0 * 128 + nsw;
                int ix1 = (kp0 + 4) * 128 + nsw;
                uint32_t h00 = sBh0[ix0], h01 = sBh0[ix1];
                uint32_t l00 = sBl0[ix0], l01 = sBl0[ix1];
                uint32_t h10 = sBh1[ix0], h11 = sBh1[ix1];
                uint32_t l10 = sBl1[ix0], l11 = sBl1[ix1];
#pragma unroll
                for (int mt = 0; mt < 2; mt++) {
                    mma16816(acc0[mt][nt], ah[mt], h00, h01);
                    mma16816(acc0[mt][nt], ah[mt], l00, l01);
                    mma16816(acc0[mt][nt], al2[mt], h00, h01);
                    mma16816(acc1[mt][nt], ah[mt], h10, h11);
                    mma16816(acc1[mt][nt], ah[mt], l10, l11);
                    mma16816(acc1[mt][nt], al2[mt], h10, h11);
                }
            }
        }
    }

    // --- epilogue: mu, ls, z for 64 x 128 patch --------------------------------
#pragma unroll
    for (int mt = 0; mt < 2; mt++) {
        int r = rowBase + wm * 32 + mt * 16 + (l >> 2);
#pragma unroll
        for (int nt = 0; nt < 4; nt++) {
            int colb = wn * 32 + nt * 8 + 2 * (l & 3);     // local 0..127
            float bm0 = sB0[colb], bm1 = sB0[colb + 1];
            float bs0 = sB1[colb], bs1 = sB1[colb + 1];
            int gcol = colOff + colb;
#pragma unroll
            for (int half = 0; half < 2; half++) {
                int rr = r + half * 8;
                if (rr >= M) continue;
                size_t idx = (size_t)rr * 256 + gcol;
                float m0 = acc0[mt][nt][half * 2 + 0] + bm0;
                float m1 = acc0[mt][nt][half * 2 + 1] + bm1;
                float s0 = acc1[mt][nt][half * 2 + 0] + bs0;
                float s1 = acc1[mt][nt][half * 2 + 1] + bs1;
                uint2 r0 = threefry2x32(0u, 1u, 0u, (uint32_t)idx);
                uint2 r1 = threefry2x32(0u, 1u, 0u, (uint32_t)idx + 1u);
                float z0 = m0 + expf(s0) * bits_to_eps(r0.x ^ r0.y);
                float z1 = m1 + expf(s1) * bits_to_eps(r1.x ^ r1.y);
                *(float2*)(Cmu + idx) = make_float2(m0, m1);
                *(float2*)(Cls + idx) = make_float2(s0, s1);
                *(float2*)(zOut + idx) = make_float2(z0, z1);
            }
        }
    }
}

// ---------------- launch ------------------------------------------------------
extern "C" void kernel_launch(void* const* d_in, const int* in_sizes, int n_in,
                              void* d_out, int out_size) {
    const float* x   = (const float*)d_in[0];
    const int*   ei  = (const int*)d_in[1];
    const float* W1  = (const float*)d_in[2];
    const float* b1  = (const float*)d_in[3];
    const float* Wmu = (const float*)d_in[4];
    const float* bmu = (const float*)d_in[5];
    const float* Wls = (const float*)d_in[6];
    const float* bls = (const float*)d_in[7];
    int E = in_sizes[1] / 2;

    float* out = (float*)d_out;
    float* z   = out;
    float* mu  = out + (size_t)NH;
    float* ls  = out + 2 * (size_t)NH;

    float* buf1; float* buf2; int* degp; void* bhp; void* blp;
    cudaGetSymbolAddress((void**)&buf1, g_buf1);
    cudaGetSymbolAddress((void**)&buf2, g_buf2);
    cudaGetSymbolAddress((void**)&degp, g_deg);
    cudaGetSymbolAddress(&bhp, g_Bh);
    cudaGetSymbolAddress(&blp, g_Bl);
    const uint32_t* Bh = (const uint32_t*)bhp;
    const uint32_t* Bl = (const uint32_t*)blp;

    cudaFuncSetAttribute(k_gemm_mma,
                         cudaFuncAttributeMaxDynamicSharedMemorySize, SMEM_MMA);
    cudaFuncSetAttribute(k_gemm_dual2,
                         cudaFuncAttributeMaxDynamicSharedMemorySize, SMEM_MMA);

    dim3 gspmm((N_NODES + 7) / 8);
    int cntBlks = CONV_BLKS + (E + 255) / 256;

    cudaMemsetAsync(degp, 0, N_NODES * sizeof(int));
    k_count_conv<<<cntBlks, 256>>>(ei, E, W1, Wmu, Wls);
    k_scan1<<<NB_SCAN, 1024>>>();
    k_scan2<<<NB_SCAN, 1024>>>(E);
    k_fill<<<(E + 255) / 256, 256>>>(ei, E);
    // t = A_norm @ x -> buf1
    k_spmm_csr<<<gspmm, 256>>>(x, buf1);
    // h = relu(t @ W1 + b1) -> buf2
    k_gemm_mma<<<NBLK_M, 256, SMEM_MMA>>>(buf1, N_NODES, Bh, Bl, b1, buf2);
    // p = A_norm @ h -> buf1
    k_spmm_csr<<<gspmm, 256>>>(buf2, buf1);
    // mu + ls + z in one column-split dual GEMM
    k_gemm_dual2<<<2 * NBLK_M, 256, SMEM_MMA>>>(buf1, N_NODES,
                                                Bh + 32768, Bl + 32768, bmu,
                                                Bh + 65536, Bl + 65536, bls,
                                                mu, ls, z);
}